// round 2
// baseline (speedup 1.0000x reference)
#include <cuda_runtime.h>

#define N_ROWS 1024
#define M_ROWS 1024
#define DIM    512
#define BT     64    // block tile (both n and m)
#define KC     32    // k chunk
#define PAD    68    // padded row length in smem (68*4 bytes, 16B aligned, reduces conflicts)

__device__ float g_zn[N_ROWS];    // ||z_n||^2
__device__ float g_zprn[M_ROWS];  // ||zpr_m||^2

// One warp per row: squared-norm reduction.
__global__ void norms_kernel(const float* __restrict__ z, const float* __restrict__ zpr) {
    int warp = (blockIdx.x * blockDim.x + threadIdx.x) >> 5;
    int lane = threadIdx.x & 31;
    if (warp >= N_ROWS + M_ROWS) return;
    const float* src = (warp < N_ROWS) ? (z + (size_t)warp * DIM)
                                       : (zpr + (size_t)(warp - N_ROWS) * DIM);
    float s = 0.0f;
    #pragma unroll
    for (int i = 0; i < DIM / 32; ++i) {
        float v = src[i * 32 + lane];
        s = fmaf(v, v, s);
    }
    #pragma unroll
    for (int o = 16; o; o >>= 1) s += __shfl_xor_sync(0xffffffffu, s, o);
    if (lane == 0) {
        if (warp < N_ROWS) g_zn[warp] = s;
        else               g_zprn[warp - N_ROWS] = s;
    }
}

// Tiled pairwise kernel: for each (n, m) pair compute
//   l1 = sum |z[n]-zpr[m]|, dp = z[n].zpr[m], l2 = sqrt(|z|^2+|zpr|^2-2dp)
// Output layout: out[m][n][3] = {l1, l2, dp}
__global__ __launch_bounds__(256, 2)
void pair_kernel(const float* __restrict__ z,
                 const float* __restrict__ zpr,
                 float* __restrict__ out) {
    __shared__ float as[KC][PAD];  // z   chunk, transposed: as[k][n_local]
    __shared__ float bs[KC][PAD];  // zpr chunk, transposed: bs[k][m_local]

    const int tid = threadIdx.x;
    const int tx = tid & 15;   // n direction (4 rows each)
    const int ty = tid >> 4;   // m direction (4 rows each)
    const int n0 = blockIdx.x * BT;
    const int m0 = blockIdx.y * BT;

    // staging indices: 32 consecutive lanes read 32 consecutive k (coalesced 128B)
    const int lcol = tid & 31;   // k within chunk
    const int lrow = tid >> 5;   // row base, step 8

    float l1[4][4];
    float dp[4][4];
    #pragma unroll
    for (int i = 0; i < 4; ++i)
        #pragma unroll
        for (int j = 0; j < 4; ++j) { l1[i][j] = 0.0f; dp[i][j] = 0.0f; }

    for (int k0 = 0; k0 < DIM; k0 += KC) {
        #pragma unroll
        for (int r = 0; r < 8; ++r) {
            int row = lrow + r * 8;
            as[lcol][row] = z  [(size_t)(n0 + row) * DIM + k0 + lcol];
            bs[lcol][row] = zpr[(size_t)(m0 + row) * DIM + k0 + lcol];
        }
        __syncthreads();

        #pragma unroll
        for (int kk = 0; kk < KC; ++kk) {
            float4 a4 = *(const float4*)&as[kk][tx * 4];
            float4 b4 = *(const float4*)&bs[kk][ty * 4];
            float av[4] = {a4.x, a4.y, a4.z, a4.w};
            float bv[4] = {b4.x, b4.y, b4.z, b4.w};
            #pragma unroll
            for (int i = 0; i < 4; ++i) {
                #pragma unroll
                for (int j = 0; j < 4; ++j) {
                    float d = av[i] - bv[j];
                    l1[i][j] += fabsf(d);                      // FADD with |.| operand
                    dp[i][j] = fmaf(av[i], bv[j], dp[i][j]);   // FFMA
                }
            }
        }
        __syncthreads();
    }

    // epilogue: derive L2 from norms and dp
    float zn[4], zpn[4];
    #pragma unroll
    for (int i = 0; i < 4; ++i) zn[i]  = g_zn[n0 + tx * 4 + i];
    #pragma unroll
    for (int j = 0; j < 4; ++j) zpn[j] = g_zprn[m0 + ty * 4 + j];

    #pragma unroll
    for (int j = 0; j < 4; ++j) {
        #pragma unroll
        for (int i = 0; i < 4; ++i) {
            int n = n0 + tx * 4 + i;
            int m = m0 + ty * 4 + j;
            float l2sq = zn[i] + zpn[j] - 2.0f * dp[i][j];
            float l2 = sqrtf(fmaxf(l2sq, 0.0f));
            float* o = out + ((size_t)m * N_ROWS + n) * 3;
            o[0] = l1[i][j];
            o[1] = l2;
            o[2] = dp[i][j];
        }
    }
}

extern "C" void kernel_launch(void* const* d_in, const int* in_sizes, int n_in,
                              void* d_out, int out_size) {
    const float* z   = (const float*)d_in[0];
    const float* zpr = (const float*)d_in[1];
    float* out = (float*)d_out;

    // 2048 rows, 1 warp each -> 65536 threads
    norms_kernel<<<(N_ROWS + M_ROWS) * 32 / 256, 256>>>(z, zpr);

    dim3 grid(N_ROWS / BT, M_ROWS / BT);
    pair_kernel<<<grid, 256>>>(z, zpr, out);
}